// round 13
// baseline (speedup 1.0000x reference)
#include <cuda_runtime.h>
#include <cuda_bf16.h>

#define S_DIM 128
#define A_DIM 96
#define B_DIM 256
#define LX    512
#define LY    256
#define XOFF_STRIDE 640     // padded clamped xs byte-offset table per batch

#define RING_SLOTS 40
#define SLOT_W     264      // words per slot (8 chunks x 33)
#define RING_W     (RING_SLOTS * SLOT_W)   // 10560 words = 42240 B

// g_Cn[s][a] = -softmax(P,axis=1)[s][a] - 1   (c'' for D'' space)
__device__ float g_Cn[S_DIM * A_DIM];
// Per-batch gathered cost table: Gt[b][x][j] = g_Cn[x][ys[b][j]]
__device__ __align__(1024) float g_Gt[(size_t)B_DIM * S_DIM * LY];
// xoff[b][t] = xs[b][clamp(t-32, 0, xl-1)] * 1024  (byte row offset in Gt)
__device__ int g_xoff[B_DIM * XOFF_STRIDE];

__global__ void softmax_neg_kernel(const float* __restrict__ P) {
    int row  = blockIdx.x;
    int lane = threadIdx.x;
    const float* pr = P + row * A_DIM;
    float v0 = pr[lane], v1 = pr[lane + 32], v2 = pr[lane + 64];
    float m = fmaxf(v0, fmaxf(v1, v2));
    #pragma unroll
    for (int o = 16; o > 0; o >>= 1) m = fmaxf(m, __shfl_xor_sync(0xffffffffu, m, o));
    float e0 = expf(v0 - m), e1 = expf(v1 - m), e2 = expf(v2 - m);
    float s = e0 + e1 + e2;
    #pragma unroll
    for (int o = 16; o > 0; o >>= 1) s += __shfl_xor_sync(0xffffffffu, s, o);
    float inv = -1.0f / s;
    g_Cn[row * A_DIM + lane     ] = e0 * inv - 1.0f;
    g_Cn[row * A_DIM + lane + 32] = e1 * inv - 1.0f;
    g_Cn[row * A_DIM + lane + 64] = e2 * inv - 1.0f;
}

__global__ void build_kernel(const int* __restrict__ xs,
                             const int* __restrict__ ys,
                             const int* __restrict__ xlen) {
    __shared__ float sC[S_DIM * A_DIM];
    const int b   = blockIdx.x;
    const int tid = threadIdx.x;

    {
        const float4* src = (const float4*)g_Cn;
        float4*       dst = (float4*)sC;
        #pragma unroll
        for (int i = tid; i < (S_DIM * A_DIM) / 4; i += 256) dst[i] = src[i];
    }

    const int xl   = xlen[b] - 1;
    const int xcap = xl - 1;
    const int* xsb = xs + (size_t)b * LX;
    for (int t = tid; t < XOFF_STRIDE; t += 256) {
        int q = t - 32;
        int v = min(max(q, 0), xcap);
        g_xoff[b * XOFF_STRIDE + t] = xsb[v] * (LY * 4);
    }
    __syncthreads();

    const int yj = ys[(size_t)b * LY + tid];
    float* ob = g_Gt + (size_t)b * S_DIM * LY + tid;
    #pragma unroll 4
    for (int x = 0; x < S_DIM; ++x)
        ob[x * LY] = sC[x * A_DIM + yj];
}

// Produce one cost row (uniform xoff index via xq) into ring slot at pOffW.
// Layout: word w of the 256-float row is stored at  pOffW + 33*(w&7) + (w>>3).
#define PRODUCE() do {                                                         \
    int xo_ = *xq; ++xq;                                                       \
    const float4* src_ = (const float4*)(GtB + xo_);                           \
    float4 f0_ = src_[lane];                                                   \
    float4 f1_ = src_[lane + 32];                                              \
    int wb_ = pOffW + laneProdW;                                               \
    ring[wb_      ] = f0_.x; ring[wb_ + 33] = f0_.y;                           \
    ring[wb_ + 66 ] = f0_.z; ring[wb_ + 99] = f0_.w;                           \
    ring[wb_ + 16 ] = f1_.x; ring[wb_ + 49] = f1_.y;                           \
    ring[wb_ + 82 ] = f1_.z; ring[wb_ + 115] = f1_.w;                          \
    pOffW += SLOT_W; if (pOffW >= RING_W) pOffW -= RING_W;                     \
} while (0)

// One DP step: prefetch next-step costs from ring (8 conflict-free LDS.32),
// then E + Brent-Kung min-scan with carry-in B (R12-proven), shfl boundary.
#define DP_STEP(COMMIT) do {                                                   \
    float n0_ = ring[cW      ];                                                \
    float n1_ = ring[cW + 33 ];                                                \
    float n2_ = ring[cW + 66 ];                                                \
    float n3_ = ring[cW + 99 ];                                                \
    float n4_ = ring[cW + 132];                                                \
    float n5_ = ring[cW + 165];                                                \
    float n6_ = ring[cW + 198];                                                \
    float n7_ = ring[cW + 231];                                                \
    cW += SLOT_W; if (cW >= RING_W) cW -= RING_W;                              \
    float B_ = is0 ? 0.0f : Dl;                                                \
    float E0_ = fminf(D[0], bprev + c0);                                       \
    float E1_ = fminf(D[1], D[0] + c1);                                        \
    float E2_ = fminf(D[2], D[1] + c2);                                        \
    float E3_ = fminf(D[3], D[2] + c3);                                        \
    float E4_ = fminf(D[4], D[3] + c4);                                        \
    float E5_ = fminf(D[5], D[4] + c5);                                        \
    float E6_ = fminf(D[6], D[5] + c6);                                        \
    float E7_ = fminf(D[7], D[6] + c7);                                        \
    float a1_ = fminf(E0_, E1_);                                               \
    float a2_ = fminf(E2_, E3_);                                               \
    float a3_ = fminf(E4_, E5_);                                               \
    float a4_ = fminf(E6_, E7_);                                               \
    float b1_ = fminf(a1_, a2_);                                               \
    float b2_ = fminf(a3_, a4_);                                               \
    float n0c_ = fminf(B_, E0_);                                               \
    float n1c_ = fminf(B_, a1_);                                               \
    float n2c_ = fminf(n1c_, E2_);                                             \
    float n3c_ = fminf(B_, b1_);                                               \
    float n4c_ = fminf(n3c_, E4_);                                             \
    float n5c_ = fminf(n3c_, a3_);                                             \
    float n6c_ = fminf(n5c_, E6_);                                             \
    float n7c_ = fminf(n3c_, b2_);                                             \
    if (COMMIT) {                                                              \
        D[0] = n0c_; D[1] = n1c_; D[2] = n2c_; D[3] = n3c_;                    \
        D[4] = n4c_; D[5] = n5c_; D[6] = n6c_; D[7] = n7c_;                    \
    }                                                                          \
    float sh_ = __shfl_up_sync(0xffffffffu, D[7], 1);                          \
    bprev = B_;                                                                \
    Dl    = sh_;                                                               \
    c0 = n0_; c1 = n1_; c2 = n2_; c3 = n3_;                                    \
    c4 = n4_; c5 = n5_; c6 = n6_; c7 = n7_;                                    \
} while (0)

__global__ void __launch_bounds__(32, 4) dp_kernel(
    const int* __restrict__ xlen,
    const int* __restrict__ ylen,
    float* __restrict__ out)
{
    __shared__ float ring[RING_W];   // 42,240 B delay line

    const int b    = blockIdx.x;
    const int lane = threadIdx.x;
    const int xl   = xlen[b] - 1;   // target row (1..511)
    const int yl   = ylen[b] - 1;   // target col (1..255)

    const char* GtB = (const char*)(g_Gt + (size_t)b * S_DIM * LY);
    const int*  xpb = g_xoff + b * XOFF_STRIDE;

    const int t_lane = (yl - 1) >> 3;
    const int k_t    = (yl - 1) & 7;
    const int s_end  = xl + t_lane;
    const bool is0   = (lane == 0);

    const int laneProdW = (lane >> 1) + 132 * (lane & 1);

    float D[8];
    #pragma unroll
    for (int k = 0; k < 8; ++k) D[k] = 0.0f;   // row 0: D'' = 0
    float Dl = 0.0f, bprev = 0.0f;

    // ---- prefill ring with rows -30..5 (36 rows); row r uses xoff idx r+31 ----
    const int* xq = xpb + 1;            // idx 1 = row -30
    int pOffW = 10 * SLOT_W;            // slot of row -30: (-30+40)=10
    #pragma unroll 2
    for (int r = 0; r < 36; ++r) PRODUCE();
    // after loop: pOffW -> slot 6 (= row 6), xq -> idx 37 (= row 6)  [wraps ok]
    __syncwarp();

    // initial consumer registers: costs for step 1 (lane L -> row 1-L)
    int sigma0 = (lane <= 1) ? (1 - lane) : (41 - lane);
    int cW = sigma0 * SLOT_W + lane;
    float c0 = ring[cW      ], c1 = ring[cW + 33 ], c2 = ring[cW + 66 ],
          c3 = ring[cW + 99 ], c4 = ring[cW + 132], c5 = ring[cW + 165],
          c6 = ring[cW + 198], c7 = ring[cW + 231];
    cW += SLOT_W; if (cW >= RING_W) cW -= RING_W;   // now points at step-2 row

    // ---- grouped steps: group g = steps 4g+1..4g+4, produces rows 4g+6..4g+9
    const int G0    = s_end >> 2;        // full groups
    const int Gramp = min(8, G0);        // groups needing the freeze predicate

    int g = 0;
    for (; g < Gramp; ++g) {
        __syncwarp();
        PRODUCE(); PRODUCE(); PRODUCE(); PRODUCE();
        const int sb = 4 * g + 1;
        { const bool act = (sb + 0 > lane); DP_STEP(act); }
        { const bool act = (sb + 1 > lane); DP_STEP(act); }
        { const bool act = (sb + 2 > lane); DP_STEP(act); }
        { const bool act = (sb + 3 > lane); DP_STEP(act); }
    }
    for (; g < G0; ++g) {
        __syncwarp();
        PRODUCE(); PRODUCE(); PRODUCE(); PRODUCE();
        DP_STEP(true);
        DP_STEP(true);
        DP_STEP(true);
        DP_STEP(true);
    }
    __syncwarp();

    // ---- remainder (<= 3 steps), consumer-only ----
    for (int s = 4 * G0 + 1; s <= s_end; ++s) {
        const bool act = (s > lane);
        DP_STEP(act);
    }

    if (lane == t_lane) out[b] = D[k_t] + (float)(xl + yl);
}

extern "C" void kernel_launch(void* const* d_in, const int* in_sizes, int n_in,
                              void* d_out, int out_size) {
    const float* P    = (const float*)d_in[0];
    const int*   xs   = (const int*)d_in[1];
    const int*   ys   = (const int*)d_in[2];
    const int*   xlen = (const int*)d_in[3];
    const int*   ylen = (const int*)d_in[4];
    float*       out  = (float*)d_out;

    softmax_neg_kernel<<<S_DIM, 32>>>(P);
    build_kernel<<<B_DIM, 256>>>(xs, ys, xlen);
    dp_kernel<<<B_DIM, 32>>>(xlen, ylen, out);
}

// round 14
// speedup vs baseline: 1.4085x; 1.4085x over previous
#include <cuda_runtime.h>
#include <cuda_bf16.h>

#define S_DIM 128
#define A_DIM 96
#define B_DIM 256
#define LX    512
#define LY    256
#define XOFF_STRIDE 584   // padded clamped xs byte-offset table per batch

// Per-batch gathered cost table: Gt[b][x][j] = (-softmax(P)[x] - 1)[ys[b][j]]
__device__ float g_Gt[(size_t)B_DIM * S_DIM * LY];
// xoff[b][t] = xs[b][clamp(t-32, 0, xl-1)] * 1024  (byte row offset in Gt)
__device__ int   g_xoff[B_DIM * XOFF_STRIDE];

// One block per batch: softmax table in smem (8 warps x 16 rows), then
// build Gt[b] (coalesced gather) and xoff[b]. No separate softmax kernel.
__global__ void build_kernel(const float* __restrict__ P,
                             const int* __restrict__ xs,
                             const int* __restrict__ ys,
                             const int* __restrict__ xlen) {
    __shared__ float sC[S_DIM * A_DIM];
    const int b    = blockIdx.x;
    const int tid  = threadIdx.x;
    const int wid  = tid >> 5;
    const int lane = tid & 31;

    for (int row = wid; row < S_DIM; row += 8) {
        const float* pr = P + row * A_DIM;
        float v0 = pr[lane], v1 = pr[lane + 32], v2 = pr[lane + 64];
        float m = fmaxf(v0, fmaxf(v1, v2));
        #pragma unroll
        for (int o = 16; o > 0; o >>= 1) m = fmaxf(m, __shfl_xor_sync(0xffffffffu, m, o));
        float e0 = expf(v0 - m), e1 = expf(v1 - m), e2 = expf(v2 - m);
        float s = e0 + e1 + e2;
        #pragma unroll
        for (int o = 16; o > 0; o >>= 1) s += __shfl_xor_sync(0xffffffffu, s, o);
        float inv = -1.0f / s;
        sC[row * A_DIM + lane     ] = e0 * inv - 1.0f;   // c'' = -softmax - 1
        sC[row * A_DIM + lane + 32] = e1 * inv - 1.0f;
        sC[row * A_DIM + lane + 64] = e2 * inv - 1.0f;
    }

    const int xl   = xlen[b] - 1;
    const int xcap = xl - 1;
    const int* xsb = xs + (size_t)b * LX;
    for (int t = tid; t < XOFF_STRIDE; t += 256) {
        int q = t - 32;
        int v = min(max(q, 0), xcap);
        g_xoff[b * XOFF_STRIDE + t] = xsb[v] * (LY * 4);
    }
    __syncthreads();

    const int yj = ys[(size_t)b * LY + tid];
    float* ob = g_Gt + (size_t)b * S_DIM * LY + tid;
    #pragma unroll 4
    for (int x = 0; x < S_DIM; ++x)
        ob[x * LY] = sC[x * A_DIM + yj];
}

// One warp per batch, lane-skewed wavefront, D'' = D - j - r space
// (byte-identical to the proven 47.6us R10 dp kernel).
//   E''[j]   = min(D''_{r-1}[j], D''_{r-1}[j-1] + c'')
//   D''_r[j] = min(KSprefixmin(E'')[j], B)     B = D''_r[8L] (shfl; lane0: 0)

#define DP_CORE(a, bv, NA, NB, xo_, COMMIT) do {                               \
    const char* rp_ = Gtb + (xo_);                                             \
    float4 nA_ = *(const float4*)rp_;                                          \
    float4 nB_ = *(const float4*)(rp_ + 16);                                   \
    float Dl_eff = is0 ? 0.0f : Dl;                                            \
    float E0_ = fminf(D[0], bprev + (a).x);                                    \
    float E1_ = fminf(D[1], D[0] + (a).y);                                     \
    float E2_ = fminf(D[2], D[1] + (a).z);                                     \
    float E3_ = fminf(D[3], D[2] + (a).w);                                     \
    float E4_ = fminf(D[4], D[3] + (bv).x);                                    \
    float E5_ = fminf(D[5], D[4] + (bv).y);                                    \
    float E6_ = fminf(D[6], D[5] + (bv).z);                                    \
    float E7_ = fminf(D[7], D[6] + (bv).w);                                    \
    float t10_ = E0_;                                                          \
    float t11_ = fminf(E1_, E0_);                                              \
    float t12_ = fminf(E2_, E1_);                                              \
    float t13_ = fminf(E3_, E2_);                                              \
    float t14_ = fminf(E4_, E3_);                                              \
    float t15_ = fminf(E5_, E4_);                                              \
    float t16_ = fminf(E6_, E5_);                                              \
    float t17_ = fminf(E7_, E6_);                                              \
    float t20_ = t10_;                                                         \
    float t21_ = t11_;                                                         \
    float t22_ = fminf(t12_, t10_);                                            \
    float t23_ = fminf(t13_, t11_);                                            \
    float t24_ = fminf(t14_, t12_);                                            \
    float t25_ = fminf(t15_, t13_);                                            \
    float t26_ = fminf(t16_, t14_);                                            \
    float t27_ = fminf(t17_, t15_);                                            \
    if (COMMIT) {                                                              \
        D[0] = fminf(t20_, Dl_eff);                                            \
        D[1] = fminf(t21_, Dl_eff);                                            \
        D[2] = fminf(t22_, Dl_eff);                                            \
        D[3] = fminf(t23_, Dl_eff);                                            \
        D[4] = fminf(fminf(t24_, t20_), Dl_eff);                               \
        D[5] = fminf(fminf(t25_, t21_), Dl_eff);                               \
        D[6] = fminf(fminf(t26_, t22_), Dl_eff);                               \
        D[7] = fminf(fminf(t27_, t23_), Dl_eff);                               \
    }                                                                          \
    float sh_ = __shfl_up_sync(0xffffffffu, D[7], 1);                          \
    bprev = Dl_eff;                                                            \
    Dl    = sh_;                                                               \
    (NA) = nA_;  (NB) = nB_;                                                   \
} while (0)

#define DP_STEP_ROT(COMMIT) do {                                               \
    int xor_ = xo[0];                                                          \
    float4 rA_, rB_;                                                           \
    DP_CORE(cA[0], cB[0], rA_, rB_, xor_, COMMIT);                             \
    cA[0] = cA[1]; cA[1] = cA[2]; cA[2] = cA[3]; cA[3] = rA_;                  \
    cB[0] = cB[1]; cB[1] = cB[2]; cB[2] = cB[3]; cB[3] = rB_;                  \
    xo[0] = xo[1]; xo[1] = xo[2]; xo[2] = xo[3]; xo[3] = *xpr; ++xpr;          \
} while (0)

#define DP_STEP_PH(p) do {                                                     \
    DP_CORE(cA[p], cB[p], cA[p], cB[p], xo[p], true);                          \
    xo[p] = xpr[p];                                                            \
} while (0)

__global__ void __launch_bounds__(32, 4) dp_kernel(
    const int* __restrict__ xlen,
    const int* __restrict__ ylen,
    float* __restrict__ out)
{
    const int b    = blockIdx.x;
    const int lane = threadIdx.x;
    const int xl   = xlen[b] - 1;   // target row (1..511)
    const int yl   = ylen[b] - 1;   // target col (1..255)

    const char* Gtb = (const char*)(g_Gt + (size_t)b * S_DIM * LY) + lane * 32;
    const int*  xpb = g_xoff + b * XOFF_STRIDE;

    const int t_lane = (yl - 1) >> 3;
    const int k_t    = (yl - 1) & 7;
    const int s_end  = xl + t_lane;
    const bool is0   = (lane == 0);

    float D[8];
    #pragma unroll
    for (int k = 0; k < 8; ++k) D[k] = 0.0f;   // row 0: D'' = 0

    float Dl = 0.0f, bprev = 0.0f;

    // prefill: step sigma uses xoff idx sigma + 31 - lane
    float4 cA[4], cB[4];
    #pragma unroll
    for (int p = 0; p < 4; ++p) {
        int xv = xpb[32 - lane + p];            // steps 1..4
        const char* r = Gtb + xv;
        cA[p] = *(const float4*)r;
        cB[p] = *(const float4*)(r + 16);
    }
    int xo[4];
    #pragma unroll
    for (int p = 0; p < 4; ++p) xo[p] = xpb[36 - lane + p];   // steps 5..8
    const int* xpr = xpb + 40 - lane;           // steps 9.. (prefetch feed)

    // ---- ramp-in: freeze predicate live, rotating buffers ----
    int s = 1;
    const int rampEnd = min(31, s_end);
    for (; s <= rampEnd; ++s) {
        const bool act = (s > lane);
        DP_STEP_ROT(act);
    }

    // ---- steady: hand-unrolled x4, literal phases, no rotations ----
    int nSteady = s_end - s + 1;
    int n4      = nSteady & ~3;
    const int* xq_end = xpr + n4;
    for (; xpr != xq_end; xpr += 4) {
        DP_STEP_PH(0);
        DP_STEP_PH(1);
        DP_STEP_PH(2);
        DP_STEP_PH(3);
    }
    s += n4;

    // ---- remainder (<=3 steps), rotating ----
    for (; s <= s_end; ++s) {
        DP_STEP_ROT(true);
    }

    if (lane == t_lane) out[b] = D[k_t] + (float)(xl + yl);
}

extern "C" void kernel_launch(void* const* d_in, const int* in_sizes, int n_in,
                              void* d_out, int out_size) {
    const float* P    = (const float*)d_in[0];
    const int*   xs   = (const int*)d_in[1];
    const int*   ys   = (const int*)d_in[2];
    const int*   xlen = (const int*)d_in[3];
    const int*   ylen = (const int*)d_in[4];
    float*       out  = (float*)d_out;

    build_kernel<<<B_DIM, 256>>>(P, xs, ys, xlen);
    dp_kernel<<<B_DIM, 32>>>(xlen, ylen, out);
}

// round 15
// speedup vs baseline: 1.5363x; 1.0907x over previous
#include <cuda_runtime.h>
#include <cuda_bf16.h>

#define S_DIM 128
#define A_DIM 96
#define B_DIM 256
#define LX    512
#define LY    256
#define XOFF_STRIDE 584   // padded clamped xs byte-offset table per batch

// g_Cn[s][a] = -softmax(P,axis=1)[s][a] - 1   (c'' for D'' space)
__device__ float g_Cn[S_DIM * A_DIM];
// Per-batch gathered cost table: Gt[b][x][j] = g_Cn[x][ys[b][j]]
__device__ float g_Gt[(size_t)B_DIM * S_DIM * LY];
// xoff[b][t] = xs[b][clamp(t-32, 0, xl-1)] * 1024  (byte row offset in Gt)
__device__ int   g_xoff[B_DIM * XOFF_STRIDE];

__global__ void softmax_neg_kernel(const float* __restrict__ P) {
    int row  = blockIdx.x;
    int lane = threadIdx.x;
    const float* pr = P + row * A_DIM;
    float v0 = pr[lane], v1 = pr[lane + 32], v2 = pr[lane + 64];
    float m = fmaxf(v0, fmaxf(v1, v2));
    #pragma unroll
    for (int o = 16; o > 0; o >>= 1) m = fmaxf(m, __shfl_xor_sync(0xffffffffu, m, o));
    float e0 = expf(v0 - m), e1 = expf(v1 - m), e2 = expf(v2 - m);
    float s = e0 + e1 + e2;
    #pragma unroll
    for (int o = 16; o > 0; o >>= 1) s += __shfl_xor_sync(0xffffffffu, s, o);
    float inv = -1.0f / s;
    g_Cn[row * A_DIM + lane     ] = e0 * inv - 1.0f;
    g_Cn[row * A_DIM + lane + 32] = e1 * inv - 1.0f;
    g_Cn[row * A_DIM + lane + 64] = e2 * inv - 1.0f;
}

// One block per batch: build Gt[b] (gather through smem) and xoff[b].
__global__ void build_kernel(const int* __restrict__ xs,
                             const int* __restrict__ ys,
                             const int* __restrict__ xlen) {
    __shared__ float sC[S_DIM * A_DIM];
    const int b   = blockIdx.x;
    const int tid = threadIdx.x;

    {   // stage cost table (12288 floats = 3072 float4)
        const float4* src = (const float4*)g_Cn;
        float4*       dst = (float4*)sC;
        #pragma unroll
        for (int i = tid; i < (S_DIM * A_DIM) / 4; i += 256) dst[i] = src[i];
    }

    const int xl   = xlen[b] - 1;
    const int xcap = xl - 1;
    const int* xsb = xs + (size_t)b * LX;
    for (int t = tid; t < XOFF_STRIDE; t += 256) {
        int q = t - 32;
        int v = min(max(q, 0), xcap);
        g_xoff[b * XOFF_STRIDE + t] = xsb[v] * (LY * 4);
    }
    __syncthreads();

    const int yj = ys[(size_t)b * LY + tid];
    float* ob = g_Gt + (size_t)b * S_DIM * LY + tid;
    #pragma unroll 4
    for (int x = 0; x < S_DIM; ++x)
        ob[x * LY] = sC[x * A_DIM + yj];
}

// One warp per batch (256 x 1-warp blocks), lane-skewed wavefront,
// D'' = D - j - r space.
//   E''[j]   = min(D''_{r-1}[j], D''_{r-1}[j-1] + c'')
//   D''_r[j] = min(B, E''[8L+1..j])   B = D''_r[8L] (shfl; lane0: 0)
// Prefix via Brent-Kung min-scan with carry-in B: 14 FMNMX, B->D[7] depth 2.

#define DP_CORE(a, bv, NA, NB, xo_, COMMIT) do {                               \
    const char* rp_ = Gtb + (xo_);                                             \
    float4 nA_ = *(const float4*)rp_;                                          \
    float4 nB_ = *(const float4*)(rp_ + 16);                                   \
    float B_ = is0 ? 0.0f : Dl;                                                \
    float E0_ = fminf(D[0], bprev + (a).x);                                    \
    float E1_ = fminf(D[1], D[0] + (a).y);                                     \
    float E2_ = fminf(D[2], D[1] + (a).z);                                     \
    float E3_ = fminf(D[3], D[2] + (a).w);                                     \
    float E4_ = fminf(D[4], D[3] + (bv).x);                                    \
    float E5_ = fminf(D[5], D[4] + (bv).y);                                    \
    float E6_ = fminf(D[6], D[5] + (bv).z);                                    \
    float E7_ = fminf(D[7], D[6] + (bv).w);                                    \
    /* up-sweep */                                                             \
    float a1_ = fminf(E0_, E1_);                                               \
    float a2_ = fminf(E2_, E3_);                                               \
    float a3_ = fminf(E4_, E5_);                                               \
    float a4_ = fminf(E6_, E7_);                                               \
    float b1_ = fminf(a1_, a2_);                                               \
    float b2_ = fminf(a3_, a4_);                                               \
    /* down-sweep with carry B */                                              \
    float n0_ = fminf(B_, E0_);                                                \
    float n1_ = fminf(B_, a1_);                                                \
    float n2_ = fminf(n1_, E2_);                                               \
    float n3_ = fminf(B_, b1_);                                                \
    float n4_ = fminf(n3_, E4_);                                               \
    float n5_ = fminf(n3_, a3_);                                               \
    float n6_ = fminf(n5_, E6_);                                               \
    float n7_ = fminf(n3_, b2_);                                               \
    if (COMMIT) {                                                              \
        D[0] = n0_; D[1] = n1_; D[2] = n2_; D[3] = n3_;                        \
        D[4] = n4_; D[5] = n5_; D[6] = n6_; D[7] = n7_;                        \
    }                                                                          \
    float sh_ = __shfl_up_sync(0xffffffffu, D[7], 1);                          \
    bprev = B_;                                                                \
    Dl    = sh_;                                                               \
    (NA) = nA_;  (NB) = nB_;                                                   \
} while (0)

#define DP_STEP_ROT(COMMIT) do {                                               \
    int xor_ = xo[0];                                                          \
    float4 rA_, rB_;                                                           \
    DP_CORE(cA[0], cB[0], rA_, rB_, xor_, COMMIT);                             \
    cA[0] = cA[1]; cA[1] = cA[2]; cA[2] = cA[3]; cA[3] = rA_;                  \
    cB[0] = cB[1]; cB[1] = cB[2]; cB[2] = cB[3]; cB[3] = rB_;                  \
    xo[0] = xo[1]; xo[1] = xo[2]; xo[2] = xo[3]; xo[3] = *xpr; ++xpr;          \
} while (0)

#define DP_STEP_PH(p) do {                                                     \
    DP_CORE(cA[p], cB[p], cA[p], cB[p], xo[p], true);                          \
    xo[p] = xpr[p];                                                            \
} while (0)

__global__ void __launch_bounds__(32, 4) dp_kernel(
    const int* __restrict__ xlen,
    const int* __restrict__ ylen,
    float* __restrict__ out)
{
    const int b    = blockIdx.x;
    const int lane = threadIdx.x;
    const int xl   = xlen[b] - 1;   // target row (1..511)
    const int yl   = ylen[b] - 1;   // target col (1..255)

    const char* Gtb = (const char*)(g_Gt + (size_t)b * S_DIM * LY) + lane * 32;
    const int*  xpb = g_xoff + b * XOFF_STRIDE;

    const int t_lane = (yl - 1) >> 3;
    const int k_t    = (yl - 1) & 7;
    const int s_end  = xl + t_lane;
    const bool is0   = (lane == 0);

    float D[8];
    #pragma unroll
    for (int k = 0; k < 8; ++k) D[k] = 0.0f;   // row 0: D'' = 0

    float Dl = 0.0f, bprev = 0.0f;

    // prefill: step sigma uses xoff idx sigma + 31 - lane
    float4 cA[4], cB[4];
    #pragma unroll
    for (int p = 0; p < 4; ++p) {
        int xv = xpb[32 - lane + p];            // steps 1..4
        const char* r = Gtb + xv;
        cA[p] = *(const float4*)r;
        cB[p] = *(const float4*)(r + 16);
    }
    int xo[4];
    #pragma unroll
    for (int p = 0; p < 4; ++p) xo[p] = xpb[36 - lane + p];   // steps 5..8
    const int* xpr = xpb + 40 - lane;           // steps 9.. (prefetch feed)

    // ---- ramp-in: freeze predicate live, rotating buffers ----
    int s = 1;
    const int rampEnd = min(31, s_end);
    for (; s <= rampEnd; ++s) {
        const bool act = (s > lane);
        DP_STEP_ROT(act);
    }

    // ---- steady: hand-unrolled x4, literal phases, no rotations ----
    int nSteady = s_end - s + 1;
    int n4      = nSteady & ~3;
    const int* xq_end = xpr + n4;
    for (; xpr != xq_end; xpr += 4) {
        DP_STEP_PH(0);
        DP_STEP_PH(1);
        DP_STEP_PH(2);
        DP_STEP_PH(3);
    }
    s += n4;

    // ---- remainder (<=3 steps), rotating ----
    for (; s <= s_end; ++s) {
        DP_STEP_ROT(true);
    }

    if (lane == t_lane) out[b] = D[k_t] + (float)(xl + yl);
}

extern "C" void kernel_launch(void* const* d_in, const int* in_sizes, int n_in,
                              void* d_out, int out_size) {
    const float* P    = (const float*)d_in[0];
    const int*   xs   = (const int*)d_in[1];
    const int*   ys   = (const int*)d_in[2];
    const int*   xlen = (const int*)d_in[3];
    const int*   ylen = (const int*)d_in[4];
    float*       out  = (float*)d_out;

    softmax_neg_kernel<<<S_DIM, 32>>>(P);
    build_kernel<<<B_DIM, 256>>>(xs, ys, xlen);
    dp_kernel<<<B_DIM, 32>>>(xlen, ylen, out);
}